// round 15
// baseline (speedup 1.0000x reference)
#include <cuda_runtime.h>
#include <cuda_fp16.h>
#include <cstdint>
#include <cstddef>

#define NB    16
#define CC    192
#define HH    56
#define WW    56
#define HWP   (HH*WW)          // 3136
#define NPIX  (NB*HWP)         // 50176
#define HEADS 6
#define CHN   32
#define KT    486              // 81 * 6
#define KTP   648              // padded: 54 groups * 12
#define SCALE 0.17677669529663689f   // 32^-0.5

// ---------------- scratch (device globals; no runtime allocation) -------------
__device__ float  g_v   [NB*CC*HWP];                 // value projection    (38.5 MB)
// att layout: [n][head][kout][pixel][12] in FP16 (65 MB, plane-major)
__device__ __half g_att [(size_t)NB*HEADS*9*HWP*12];
__device__ float  g_fold[NB*CC*HWP];                 // folded result       (38.5 MB)
__device__ __half g_wpad[CC*KTP];                    // padded Wa, FP16     (249 KB)

// ---------------- packed f32x2 helpers ---------------------------------------
#define FMA2(acc,a,b) asm("fma.rn.f32x2 %0, %1, %2, %0;" : "+l"(acc) : "l"(a), "l"(b))

__device__ __forceinline__ unsigned long long pack2(float x, float y) {
    unsigned long long r;
    asm("mov.b64 %0, {%1, %2};" : "=l"(r) : "r"(__float_as_uint(x)), "r"(__float_as_uint(y)));
    return r;
}
__device__ __forceinline__ void unpack2(unsigned long long v, float& x, float& y) {
    unsigned int lo, hi;
    asm("mov.b64 {%0, %1}, %2;" : "=r"(lo), "=r"(hi) : "l"(v));
    x = __uint_as_float(lo); y = __uint_as_float(hi);
}

// ---------------- cp.async helpers -------------------------------------------
__device__ __forceinline__ void cp_async16(void* smem_ptr, const void* gptr) {
    unsigned int saddr = (unsigned int)__cvta_generic_to_shared(smem_ptr);
    asm volatile("cp.async.cg.shared.global [%0], [%1], 16;"
                 :: "r"(saddr), "l"(gptr) : "memory");
}
#define CP_COMMIT() asm volatile("cp.async.commit_group;" ::: "memory")
#define CP_WAIT0()  asm volatile("cp.async.wait_group 0;" ::: "memory")

// ============================================================================
// Wa pre-pad + FP16 convert: [192][486] fp32 -> [192][648] half.
// ============================================================================
__global__ void pad_wa_kernel(const float* __restrict__ Wa, __half* __restrict__ Wp)
{
    int i = blockIdx.x * 256 + threadIdx.x;
    if (i >= CC*KTP) return;
    int c = i / KTP, col = i - c*KTP;
    int g = col / 12, u = col - g*12;
    Wp[i] = (u < 9) ? __float2half(Wa[c*KT + g*9 + u]) : __float2half(0.0f);
}

// ============================================================================
// Kernel A/D: 192x192 pointwise GEMM. Exact R8 version.
// ============================================================================
__global__ void __launch_bounds__(192, 3) gemm192_kernel(
    const float* __restrict__ X, const float* __restrict__ Wm,
    const float* __restrict__ bias, float* __restrict__ Out)
{
    __shared__ float xs[48][128];
    __shared__ float ws[48][96];
    const int tid  = threadIdx.x;
    const int b    = blockIdx.x;
    const int pt   = b >> 1;
    const int dt   = b & 1;
    const int g0   = pt * 128;
    const int dbase= dt * 96;
    const int warp = tid >> 5, lane = tid & 31;
    const int wd   = warp % 3, wp = warp / 3;
    const int ld   = lane >> 3, lp = lane & 7;
    const int d0   = wd*32 + ld*8;
    const int p0   = wp*64 + lp*8;

    unsigned long long acc[8][4];
    #pragma unroll
    for (int di = 0; di < 8; di++) {
        float bb = bias ? bias[dbase + d0 + di] : 0.0f;
        unsigned long long b2 = pack2(bb, bb);
        #pragma unroll
        for (int pp = 0; pp < 4; pp++) acc[di][pp] = b2;
    }

    for (int kc = 0; kc < 4; kc++) {
        __syncthreads();
        #pragma unroll
        for (int s = 0; s < 8; s++) {
            int idx = tid + s*192;
            int k = idx >> 5, p4 = idx & 31;
            int g = g0 + p4*4;
            int n = g / HWP, hw = g - n*HWP;
            *(float4*)&xs[k][p4*4] =
                *(const float4*)&X[((size_t)(n*CC) + kc*48 + k)*HWP + hw];
        }
        #pragma unroll
        for (int s = 0; s < 6; s++) {
            int idx = tid + s*192;
            int k = idx / 24, c4 = idx - k*24;
            *(float4*)&ws[k][c4*4] =
                *(const float4*)&Wm[(size_t)(kc*48 + k)*192 + dbase + c4*4];
        }
        __syncthreads();

        #pragma unroll 4
        for (int r = 0; r < 48; r++) {
            float4 wa = *(const float4*)&ws[r][d0];
            float4 wb = *(const float4*)&ws[r][d0+4];
            ulonglong2 xv0 = *(const ulonglong2*)&xs[r][p0];
            ulonglong2 xv1 = *(const ulonglong2*)&xs[r][p0+4];
            unsigned long long xp[4] = {xv0.x, xv0.y, xv1.x, xv1.y};
            unsigned long long w2[8];
            w2[0]=pack2(wa.x,wa.x); w2[1]=pack2(wa.y,wa.y);
            w2[2]=pack2(wa.z,wa.z); w2[3]=pack2(wa.w,wa.w);
            w2[4]=pack2(wb.x,wb.x); w2[5]=pack2(wb.y,wb.y);
            w2[6]=pack2(wb.z,wb.z); w2[7]=pack2(wb.w,wb.w);
            #pragma unroll
            for (int di = 0; di < 8; di++)
                #pragma unroll
                for (int pp = 0; pp < 4; pp++)
                    FMA2(acc[di][pp], xp[pp], w2[di]);
        }
    }

    #pragma unroll
    for (int s = 0; s < 2; s++) {
        int g = g0 + p0 + s*4;
        int n = g / HWP, hw = g - n*HWP;
        #pragma unroll
        for (int di = 0; di < 8; di++) {
            ulonglong2 uv; uv.x = acc[di][2*s]; uv.y = acc[di][2*s+1];
            *(ulonglong2*)&Out[((size_t)(n*CC) + dbase + d0 + di)*HWP + hw] = uv;
        }
    }
}

// ============================================================================
// Kernel B: attention logits GEMM + fused register softmax.
// cp.async double-buffered; Wa now FP16 in smem (fill ops per chunk halved:
// 5184 -> 2592 -> fill ~5.7K cyc/SMSP, fully hidden under ~8.9K compute).
// Inner loop: 3x LDS.64 (12 halfs) + H2F converts + packs + 18 FMA2.
// smem = 2 x (8KB x + 41.5KB w) = 99.3KB.
// ============================================================================
#define ATT_XS_FLOATS (32*64)
#define ATT_BUF_BYTES (32*64*4 + 32*KTP*2)       // 49664
#define ATT_SMEM_BYTES (2*ATT_BUF_BYTES)         // 99328

__global__ void __launch_bounds__(864, 1) att_kernel(
    const float* __restrict__ X, const __half* __restrict__ Wpad,
    const float* __restrict__ ba, __half* __restrict__ Att)
{
    extern __shared__ char asmem[];
    const int tid = threadIdx.x;
    const int cg  = tid >> 4;       // 0..53  (= head*9 + kout)
    const int pg  = tid & 15;       // 0..15 -> px [4pg, 4pg+4)
    const int bb  = blockIdx.x;
    const int n   = bb / 49;
    const int hw0 = (bb - n*49) * 64;

    // async fill of one buffer for K-chunk kc
    auto fill = [&](int kc, int buf) {
        char* base = asmem + buf*ATT_BUF_BYTES;
        float*  xsb = (float*)base;                       // [32][64] fp32
        __half* wsb = (__half*)(base + ATT_XS_FLOATS*4);  // [32][648] half
        if (tid < 512) {
            int k = tid >> 4, p4 = tid & 15;
            cp_async16(&xsb[k*64 + p4*4],
                       &X[((size_t)(n*CC) + kc*32 + k)*HWP + hw0 + p4*4]);
        }
        // ws: 32 rows x 1296B = 2592 16B chunks -> 3 per thread
        #pragma unroll
        for (int s = 0; s < 3; s++) {
            int idx = tid + s*864;
            int k = idx / 81, c4 = idx - k*81;
            cp_async16(&wsb[k*KTP + c4*8],
                       &Wpad[(size_t)(kc*32 + k)*KTP + c4*8]);
        }
    };

    unsigned long long acc[9][2];
    #pragma unroll
    for (int u = 0; u < 9; u++) {
        float bv = ba[9*cg + u];
        unsigned long long b2 = pack2(bv, bv);
        acc[u][0] = b2; acc[u][1] = b2;
    }

    fill(0, 0); CP_COMMIT(); CP_WAIT0();
    __syncthreads();

    for (int kc = 0; kc < 6; kc++) {
        const int buf = kc & 1;
        if (kc < 5) { fill(kc + 1, buf ^ 1); CP_COMMIT(); }

        const char* base = asmem + buf*ATT_BUF_BYTES;
        const float*  xs = (const float*)base;
        const __half* ws = (const __half*)(base + ATT_XS_FLOATS*4);

        #pragma unroll 2
        for (int r = 0; r < 32; r++) {
            const __half* wr = ws + r*KTP + 12*cg;        // 24B*cg -> 8B aligned
            uint2 wa_ = *(const uint2*)(wr);              // halfs 0..3
            uint2 wb_ = *(const uint2*)(wr + 4);          // halfs 4..7
            unsigned int wc_ = *(const unsigned int*)(wr + 8);  // half 8 + pad
            float2 f01 = __half22float2(*(const __half2*)&wa_.x);
            float2 f23 = __half22float2(*(const __half2*)&wa_.y);
            float2 f45 = __half22float2(*(const __half2*)&wb_.x);
            float2 f67 = __half22float2(*(const __half2*)&wb_.y);
            float  f8  = __low2float(*(const __half2*)&wc_);
            float wv[9] = {f01.x, f01.y, f23.x, f23.y,
                           f45.x, f45.y, f67.x, f67.y, f8};

            ulonglong2 xv = *(const ulonglong2*)&xs[r*64 + 4*pg];
            unsigned long long xp0 = xv.x, xp1 = xv.y;
            #pragma unroll
            for (int u = 0; u < 9; u++) {
                unsigned long long w2 = pack2(wv[u], wv[u]);
                FMA2(acc[u][0], xp0, w2);
                FMA2(acc[u][1], xp1, w2);
            }
        }

        if (kc < 5) CP_WAIT0();
        __syncthreads();
    }

    __half* planeBase = Att + ((size_t)n*54 + cg)*HWP*12;

    #pragma unroll
    for (int pp = 0; pp < 2; pp++) {
        float z0[9], z1[9];
        #pragma unroll
        for (int u = 0; u < 9; u++) unpack2(acc[u][pp], z0[u], z1[u]);
        #pragma unroll
        for (int half = 0; half < 2; half++) {
            float* z = half ? z1 : z0;
            float m = z[0];
            #pragma unroll
            for (int u = 1; u < 9; u++) m = fmaxf(m, z[u]);
            float e[9], s = 0.0f;
            #pragma unroll
            for (int u = 0; u < 9; u++) { e[u] = __expf((z[u]-m)*SCALE); s += e[u]; }
            float inv = 1.0f / s;
            int px = 4*pg + 2*pp + half;
            __half* dst = planeBase + (size_t)(hw0 + px)*12;
            __half2 h01 = __floats2half2_rn(e[0]*inv, e[1]*inv);
            __half2 h23 = __floats2half2_rn(e[2]*inv, e[3]*inv);
            __half2 h45 = __floats2half2_rn(e[4]*inv, e[5]*inv);
            __half2 h67 = __floats2half2_rn(e[6]*inv, e[7]*inv);
            __half2 h8x = __floats2half2_rn(e[8]*inv, 0.0f);
            __half2 hxx = __floats2half2_rn(0.0f, 0.0f);
            uint2 u0, u1, u2;
            u0.x = *(unsigned int*)&h01; u0.y = *(unsigned int*)&h23;
            u1.x = *(unsigned int*)&h45; u1.y = *(unsigned int*)&h67;
            u2.x = *(unsigned int*)&h8x; u2.y = *(unsigned int*)&hxx;
            *(uint2*)(dst)     = u0;
            *(uint2*)(dst + 4) = u1;
            *(uint2*)(dst + 8) = u2;
        }
    }
}

// ============================================================================
// Kernel C: aggregation + fold, 5x5 collapsed stencil. Exact R8 version.
// ============================================================================
#define AGG_SMEM_BYTES (96*145*8)                // 111360

__global__ void __launch_bounds__(384, 2) agg_kernel(
    const float* __restrict__ V, const __half* __restrict__ Att,
    float* __restrict__ Fold)
{
    extern __shared__ char smraw[];
    unsigned long long* vsm2 = (unsigned long long*)smraw;      // [96][145]
    const int tid = threadIdx.x;
    const int blk = blockIdx.x;
    const int n   = blk / 49;
    const int tt  = blk - n*49;
    const int y0  = (tt / 7) * 8, x0 = (tt % 7) * 8;

    for (int i = tid; i < 96*144; i += 384) {
        int cp = i / 144, pos = i - cp*144;
        int ly = pos / 12, lx = pos - ly*12;
        int gy = y0 - 2 + ly, gx = x0 - 2 + lx;
        float a = 0.0f, b = 0.0f;
        if (gy >= 0 && gy < HH && gx >= 0 && gx < WW) {
            const float* vb = &V[((size_t)(n*CC) + 2*cp)*HWP + gy*WW + gx];
            a = vb[0]; b = vb[HWP];
        }
        vsm2[cp*145 + pos] = pack2(a, b);
    }
    __syncthreads();

    {
        const int head = tid >> 6;          // 0..5
        const int q    = tid & 63;
        const int qy = q >> 3, qx = q & 7;
        const int gy = y0 + qy, gx = x0 + qx;

        float W2[25];
        #pragma unroll
        for (int p = 0; p < 25; p++) W2[p] = 0.0f;
        const __half* hbase = Att + ((size_t)n*54 + head*9)*HWP*12;
        #pragma unroll
        for (int i = 0; i < 3; i++)
        #pragma unroll
        for (int j = 0; j < 3; j++) {
            int py = gy + 1 - i, px = gx + 1 - j;
            if (py >= 0 && py < HH && px >= 0 && px < WW) {
                const __half* ab = hbase + ((size_t)(i*3+j)*HWP + py*WW + px)*12;
                uint2 u0 = *(const uint2*)(ab);
                uint2 u1 = *(const uint2*)(ab + 4);
                unsigned int u2 = *(const unsigned int*)(ab + 8);
                __half2 h01 = *(__half2*)&u0.x, h23 = *(__half2*)&u0.y;
                __half2 h45 = *(__half2*)&u1.x, h67 = *(__half2*)&u1.y;
                __half2 h8x = *(__half2*)&u2;
                float2 f01 = __half22float2(h01);
                float2 f23 = __half22float2(h23);
                float2 f45 = __half22float2(h45);
                float2 f67 = __half22float2(h67);
                float  f8  = __low2float(h8x);
                float av[9] = {f01.x, f01.y, f23.x, f23.y,
                               f45.x, f45.y, f67.x, f67.y, f8};
                #pragma unroll
                for (int a = 0; a < 3; a++)
                #pragma unroll
                for (int b = 0; b < 3; b++)
                    W2[(a-i+2)*5 + (b-j+2)] += av[a*3+b];
            }
        }

        unsigned long long acc[16];
        #pragma unroll
        for (int c16 = 0; c16 < 16; c16++) acc[c16] = 0ull;
        const unsigned long long* vbase = vsm2 + (head*16)*145 + qy*12 + qx;
        #pragma unroll
        for (int p = 0; p < 25; p++) {
            const int off = (p/5)*12 + (p%5);
            unsigned long long w2 = pack2(W2[p], W2[p]);
            #pragma unroll
            for (int c16 = 0; c16 < 16; c16++)
                FMA2(acc[c16], vbase[c16*145 + off], w2);
        }

        float* foutbase = Fold + ((size_t)(n*CC))*HWP + gy*WW + gx;
        #pragma unroll
        for (int c16 = 0; c16 < 16; c16++) {
            const int cp = head*16 + c16;
            float xa, ya;
            unpack2(acc[c16], xa, ya);
            foutbase[(size_t)(2*cp    )*HWP] = xa;
            foutbase[(size_t)(2*cp + 1)*HWP] = ya;
        }
    }
}

// ============================================================================
// Launch
// ============================================================================
extern "C" void kernel_launch(void* const* d_in, const int* in_sizes, int n_in,
                              void* d_out, int out_size)
{
    const float* x  = (const float*)d_in[0];
    const float* Wv = (const float*)d_in[1];
    const float* Wa = (const float*)d_in[2];
    const float* ba = (const float*)d_in[3];
    const float* Wp = (const float*)d_in[4];
    const float* bp = (const float*)d_in[5];
    float* out = (float*)d_out;

    float *vp, *fp;
    __half *ap, *wpad;
    cudaGetSymbolAddress((void**)&vp, g_v);
    cudaGetSymbolAddress((void**)&ap, g_att);
    cudaGetSymbolAddress((void**)&fp, g_fold);
    cudaGetSymbolAddress((void**)&wpad, g_wpad);

    cudaFuncSetAttribute(att_kernel, cudaFuncAttributeMaxDynamicSharedMemorySize, ATT_SMEM_BYTES);
    cudaFuncSetAttribute(agg_kernel, cudaFuncAttributeMaxDynamicSharedMemorySize, AGG_SMEM_BYTES);

    // pad Wa -> [192][648] fp16
    pad_wa_kernel<<<(CC*KTP + 255)/256, 256>>>(Wa, wpad);
    // value projection: v = x @ Wv
    gemm192_kernel<<<392*2, 192>>>(x, Wv, nullptr, vp);
    // attention logits + fused softmax (fp16 Wa, cp.async double-buffered)
    att_kernel<<<NB*49, 864, ATT_SMEM_BYTES>>>(x, wpad, ba, ap);
    // aggregation + fold (collapsed 5x5 stencil, fp16 att gather)
    agg_kernel<<<NB*49, 384, AGG_SMEM_BYTES>>>(vp, ap, fp);
    // output projection: out = folded @ Wp + bp
    gemm192_kernel<<<392*2, 192>>>(fp, Wp, bp, out);
}

// round 16
// speedup vs baseline: 1.0619x; 1.0619x over previous
#include <cuda_runtime.h>
#include <cuda_fp16.h>
#include <cstdint>
#include <cstddef>

#define NB    16
#define CC    192
#define HH    56
#define WW    56
#define HWP   (HH*WW)          // 3136
#define NPIX  (NB*HWP)         // 50176
#define HEADS 6
#define CHN   32
#define KT    486              // 81 * 6
#define KTP   648              // padded: 54 groups * 12
#define SCALE 0.17677669529663689f   // 32^-0.5

// ---------------- scratch (device globals; no runtime allocation) -------------
__device__ float  g_v   [NB*CC*HWP];                 // value projection    (38.5 MB)
// att layout: [n][head][kout][pixel][12] in FP16 (65 MB, plane-major)
__device__ __half g_att [(size_t)NB*HEADS*9*HWP*12];
__device__ float  g_fold[NB*CC*HWP];                 // folded result       (38.5 MB)
__device__ float  g_wpad[CC*KTP];                    // padded Wa, fp32     (497 KB)

// ---------------- packed f32x2 helpers ---------------------------------------
#define FMA2(acc,a,b) asm("fma.rn.f32x2 %0, %1, %2, %0;" : "+l"(acc) : "l"(a), "l"(b))

__device__ __forceinline__ unsigned long long pack2(float x, float y) {
    unsigned long long r;
    asm("mov.b64 %0, {%1, %2};" : "=l"(r) : "r"(__float_as_uint(x)), "r"(__float_as_uint(y)));
    return r;
}
__device__ __forceinline__ void unpack2(unsigned long long v, float& x, float& y) {
    unsigned int lo, hi;
    asm("mov.b64 {%0, %1}, %2;" : "=r"(lo), "=r"(hi) : "l"(v));
    x = __uint_as_float(lo); y = __uint_as_float(hi);
}

// ---------------- cp.async helpers -------------------------------------------
__device__ __forceinline__ void cp_async16(void* smem_ptr, const void* gptr) {
    unsigned int saddr = (unsigned int)__cvta_generic_to_shared(smem_ptr);
    asm volatile("cp.async.cg.shared.global [%0], [%1], 16;"
                 :: "r"(saddr), "l"(gptr) : "memory");
}
#define CP_COMMIT() asm volatile("cp.async.commit_group;" ::: "memory")
#define CP_WAIT0()  asm volatile("cp.async.wait_group 0;" ::: "memory")

// ============================================================================
// Wa pre-pad: [192][486] fp32 -> [192][648] fp32 (group g at 12g..12g+8).
// ============================================================================
__global__ void pad_wa_kernel(const float* __restrict__ Wa, float* __restrict__ Wp)
{
    int i = blockIdx.x * 256 + threadIdx.x;
    if (i >= CC*KTP) return;
    int c = i / KTP, col = i - c*KTP;
    int g = col / 12, u = col - g*12;
    Wp[i] = (u < 9) ? Wa[c*KT + g*9 + u] : 0.0f;
}

// ============================================================================
// Kernel A/D: 192x192 pointwise GEMM. Exact R8 version.
// ============================================================================
__global__ void __launch_bounds__(192, 3) gemm192_kernel(
    const float* __restrict__ X, const float* __restrict__ Wm,
    const float* __restrict__ bias, float* __restrict__ Out)
{
    __shared__ float xs[48][128];
    __shared__ float ws[48][96];
    const int tid  = threadIdx.x;
    const int b    = blockIdx.x;
    const int pt   = b >> 1;
    const int dt   = b & 1;
    const int g0   = pt * 128;
    const int dbase= dt * 96;
    const int warp = tid >> 5, lane = tid & 31;
    const int wd   = warp % 3, wp = warp / 3;
    const int ld   = lane >> 3, lp = lane & 7;
    const int d0   = wd*32 + ld*8;
    const int p0   = wp*64 + lp*8;

    unsigned long long acc[8][4];
    #pragma unroll
    for (int di = 0; di < 8; di++) {
        float bb = bias ? bias[dbase + d0 + di] : 0.0f;
        unsigned long long b2 = pack2(bb, bb);
        #pragma unroll
        for (int pp = 0; pp < 4; pp++) acc[di][pp] = b2;
    }

    for (int kc = 0; kc < 4; kc++) {
        __syncthreads();
        #pragma unroll
        for (int s = 0; s < 8; s++) {
            int idx = tid + s*192;
            int k = idx >> 5, p4 = idx & 31;
            int g = g0 + p4*4;
            int n = g / HWP, hw = g - n*HWP;
            *(float4*)&xs[k][p4*4] =
                *(const float4*)&X[((size_t)(n*CC) + kc*48 + k)*HWP + hw];
        }
        #pragma unroll
        for (int s = 0; s < 6; s++) {
            int idx = tid + s*192;
            int k = idx / 24, c4 = idx - k*24;
            *(float4*)&ws[k][c4*4] =
                *(const float4*)&Wm[(size_t)(kc*48 + k)*192 + dbase + c4*4];
        }
        __syncthreads();

        #pragma unroll 4
        for (int r = 0; r < 48; r++) {
            float4 wa = *(const float4*)&ws[r][d0];
            float4 wb = *(const float4*)&ws[r][d0+4];
            ulonglong2 xv0 = *(const ulonglong2*)&xs[r][p0];
            ulonglong2 xv1 = *(const ulonglong2*)&xs[r][p0+4];
            unsigned long long xp[4] = {xv0.x, xv0.y, xv1.x, xv1.y};
            unsigned long long w2[8];
            w2[0]=pack2(wa.x,wa.x); w2[1]=pack2(wa.y,wa.y);
            w2[2]=pack2(wa.z,wa.z); w2[3]=pack2(wa.w,wa.w);
            w2[4]=pack2(wb.x,wb.x); w2[5]=pack2(wb.y,wb.y);
            w2[6]=pack2(wb.z,wb.z); w2[7]=pack2(wb.w,wb.w);
            #pragma unroll
            for (int di = 0; di < 8; di++)
                #pragma unroll
                for (int pp = 0; pp < 4; pp++)
                    FMA2(acc[di][pp], xp[pp], w2[di]);
        }
    }

    #pragma unroll
    for (int s = 0; s < 2; s++) {
        int g = g0 + p0 + s*4;
        int n = g / HWP, hw = g - n*HWP;
        #pragma unroll
        for (int di = 0; di < 8; di++) {
            ulonglong2 uv; uv.x = acc[di][2*s]; uv.y = acc[di][2*s+1];
            *(ulonglong2*)&Out[((size_t)(n*CC) + dbase + d0 + di)*HWP + hw] = uv;
        }
    }
}

// ============================================================================
// Kernel B: attention logits GEMM + fused register softmax.
// NEW TILING: block = 128 pixels x 27 column-groups (half of 54).
//   - Wa fill per block-chunk: 2592 float4 (was 5184) -> fill ~7.2K cyc/SMSP
//     < compute ~8K -> fully hidden by cp.async double-buffering.
//   - cg = tid>>5: each WARP owns one column group -> weight LDS are
//     uniform/broadcast (1 wavefront each).
//   - 128-px tiles cross image borders: per-float4 g/HWP flattening (HWP%4==0).
// Inner loop datatypes identical to the proven R8/R13 compute.
// smem = 2 x (16KB xs + 40.5KB ws) = 113KB.
// ============================================================================
#define ATT_XS_FLOATS (32*128)
#define ATT_WS_FLOATS (32*324)
#define ATT_BUF_FLOATS (ATT_XS_FLOATS + ATT_WS_FLOATS)   // 14464
#define ATT_SMEM_BYTES (2*ATT_BUF_FLOATS*4)              // 115712

__global__ void __launch_bounds__(864, 1) att_kernel(
    const float* __restrict__ X, const float* __restrict__ Wpad,
    const float* __restrict__ ba, __half* __restrict__ Att)
{
    extern __shared__ float sm[];
    const int tid = threadIdx.x;
    const int cg  = tid >> 5;       // 0..26  local column group (one per warp)
    const int pg  = tid & 31;       // 0..31 -> px [4pg, 4pg+4)
    const int bb  = blockIdx.x;
    const int ct  = bb & 1;         // column half
    const int pt  = bb >> 1;        // 0..391 pixel tile
    const int g0  = pt * 128;       // flattened pixel base
    const int grp = ct*27 + cg;     // global group (= head*9 + kout)

    // async fill of one buffer for K-chunk kc
    auto fill = [&](int kc, int buf) {
        float* xsb = sm + buf*ATT_BUF_FLOATS;          // [32][128]
        float* wsb = xsb + ATT_XS_FLOATS;              // [32][324]
        // xs: 1024 float4
        #pragma unroll
        for (int s = 0; s < 2; s++) {
            int idx = tid + s*864;
            if (idx < 1024) {
                int k = idx >> 5, p4 = idx & 31;
                int g = g0 + p4*4;
                int n = g / HWP, hw = g - n*HWP;
                cp_async16(&xsb[k*128 + p4*4],
                           &X[((size_t)(n*CC) + kc*32 + k)*HWP + hw]);
            }
        }
        // ws: 32 x 324 = 2592 float4 -> 3 per thread
        #pragma unroll
        for (int s = 0; s < 3; s++) {
            int idx = tid + s*864;
            int k = idx / 81, c4 = idx - k*81;
            cp_async16(&wsb[k*324 + c4*4],
                       &Wpad[(size_t)(kc*32 + k)*KTP + ct*324 + c4*4]);
        }
    };

    unsigned long long acc[9][2];
    #pragma unroll
    for (int u = 0; u < 9; u++) {
        float bv = ba[9*grp + u];
        unsigned long long b2 = pack2(bv, bv);
        acc[u][0] = b2; acc[u][1] = b2;
    }

    fill(0, 0); CP_COMMIT(); CP_WAIT0();
    __syncthreads();

    for (int kc = 0; kc < 6; kc++) {
        const int buf = kc & 1;
        if (kc < 5) { fill(kc + 1, buf ^ 1); CP_COMMIT(); }

        const float* xs = sm + buf*ATT_BUF_FLOATS;
        const float* ws = xs + ATT_XS_FLOATS;

        #pragma unroll 2
        for (int r = 0; r < 32; r++) {
            float4 q0 = *(const float4*)&ws[r*324 + 12*cg];
            float4 q1 = *(const float4*)&ws[r*324 + 12*cg + 4];
            float  q8 = ws[r*324 + 12*cg + 8];
            ulonglong2 xv = *(const ulonglong2*)&xs[r*128 + 4*pg];
            unsigned long long xp0 = xv.x, xp1 = xv.y;
            float wv[9] = {q0.x,q0.y,q0.z,q0.w,q1.x,q1.y,q1.z,q1.w,q8};
            #pragma unroll
            for (int u = 0; u < 9; u++) {
                unsigned long long w2 = pack2(wv[u], wv[u]);
                FMA2(acc[u][0], xp0, w2);
                FMA2(acc[u][1], xp1, w2);
            }
        }

        if (kc < 5) CP_WAIT0();
        __syncthreads();
    }

    #pragma unroll
    for (int pp = 0; pp < 2; pp++) {
        float z0[9], z1[9];
        #pragma unroll
        for (int u = 0; u < 9; u++) unpack2(acc[u][pp], z0[u], z1[u]);
        #pragma unroll
        for (int half = 0; half < 2; half++) {
            float* z = half ? z1 : z0;
            float m = z[0];
            #pragma unroll
            for (int u = 1; u < 9; u++) m = fmaxf(m, z[u]);
            float e[9], s = 0.0f;
            #pragma unroll
            for (int u = 0; u < 9; u++) { e[u] = __expf((z[u]-m)*SCALE); s += e[u]; }
            float inv = 1.0f / s;
            int g = g0 + 4*pg + 2*pp + half;
            int n = g / HWP, hw = g - n*HWP;
            __half* dst = Att + ((size_t)n*54 + grp)*HWP*12 + (size_t)hw*12;
            __half2 h01 = __floats2half2_rn(e[0]*inv, e[1]*inv);
            __half2 h23 = __floats2half2_rn(e[2]*inv, e[3]*inv);
            __half2 h45 = __floats2half2_rn(e[4]*inv, e[5]*inv);
            __half2 h67 = __floats2half2_rn(e[6]*inv, e[7]*inv);
            __half2 h8x = __floats2half2_rn(e[8]*inv, 0.0f);
            __half2 hxx = __floats2half2_rn(0.0f, 0.0f);
            uint2 u0, u1, u2;
            u0.x = *(unsigned int*)&h01; u0.y = *(unsigned int*)&h23;
            u1.x = *(unsigned int*)&h45; u1.y = *(unsigned int*)&h67;
            u2.x = *(unsigned int*)&h8x; u2.y = *(unsigned int*)&hxx;
            *(uint2*)(dst)     = u0;
            *(uint2*)(dst + 4) = u1;
            *(uint2*)(dst + 8) = u2;
        }
    }
}

// ============================================================================
// Kernel C: aggregation + fold, 5x5 collapsed stencil. Exact R8 version.
// ============================================================================
#define AGG_SMEM_BYTES (96*145*8)                // 111360

__global__ void __launch_bounds__(384, 2) agg_kernel(
    const float* __restrict__ V, const __half* __restrict__ Att,
    float* __restrict__ Fold)
{
    extern __shared__ char smraw[];
    unsigned long long* vsm2 = (unsigned long long*)smraw;      // [96][145]
    const int tid = threadIdx.x;
    const int blk = blockIdx.x;
    const int n   = blk / 49;
    const int tt  = blk - n*49;
    const int y0  = (tt / 7) * 8, x0 = (tt % 7) * 8;

    for (int i = tid; i < 96*144; i += 384) {
        int cp = i / 144, pos = i - cp*144;
        int ly = pos / 12, lx = pos - ly*12;
        int gy = y0 - 2 + ly, gx = x0 - 2 + lx;
        float a = 0.0f, b = 0.0f;
        if (gy >= 0 && gy < HH && gx >= 0 && gx < WW) {
            const float* vb = &V[((size_t)(n*CC) + 2*cp)*HWP + gy*WW + gx];
            a = vb[0]; b = vb[HWP];
        }
        vsm2[cp*145 + pos] = pack2(a, b);
    }
    __syncthreads();

    {
        const int head = tid >> 6;          // 0..5
        const int q    = tid & 63;
        const int qy = q >> 3, qx = q & 7;
        const int gy = y0 + qy, gx = x0 + qx;

        float W2[25];
        #pragma unroll
        for (int p = 0; p < 25; p++) W2[p] = 0.0f;
        const __half* hbase = Att + ((size_t)n*54 + head*9)*HWP*12;
        #pragma unroll
        for (int i = 0; i < 3; i++)
        #pragma unroll
        for (int j = 0; j < 3; j++) {
            int py = gy + 1 - i, px = gx + 1 - j;
            if (py >= 0 && py < HH && px >= 0 && px < WW) {
                const __half* ab = hbase + ((size_t)(i*3+j)*HWP + py*WW + px)*12;
                uint2 u0 = *(const uint2*)(ab);
                uint2 u1 = *(const uint2*)(ab + 4);
                unsigned int u2 = *(const unsigned int*)(ab + 8);
                __half2 h01 = *(__half2*)&u0.x, h23 = *(__half2*)&u0.y;
                __half2 h45 = *(__half2*)&u1.x, h67 = *(__half2*)&u1.y;
                __half2 h8x = *(__half2*)&u2;
                float2 f01 = __half22float2(h01);
                float2 f23 = __half22float2(h23);
                float2 f45 = __half22float2(h45);
                float2 f67 = __half22float2(h67);
                float  f8  = __low2float(h8x);
                float av[9] = {f01.x, f01.y, f23.x, f23.y,
                               f45.x, f45.y, f67.x, f67.y, f8};
                #pragma unroll
                for (int a = 0; a < 3; a++)
                #pragma unroll
                for (int b = 0; b < 3; b++)
                    W2[(a-i+2)*5 + (b-j+2)] += av[a*3+b];
            }
        }

        unsigned long long acc[16];
        #pragma unroll
        for (int c16 = 0; c16 < 16; c16++) acc[c16] = 0ull;
        const unsigned long long* vbase = vsm2 + (head*16)*145 + qy*12 + qx;
        #pragma unroll
        for (int p = 0; p < 25; p++) {
            const int off = (p/5)*12 + (p%5);
            unsigned long long w2 = pack2(W2[p], W2[p]);
            #pragma unroll
            for (int c16 = 0; c16 < 16; c16++)
                FMA2(acc[c16], vbase[c16*145 + off], w2);
        }

        float* foutbase = Fold + ((size_t)(n*CC))*HWP + gy*WW + gx;
        #pragma unroll
        for (int c16 = 0; c16 < 16; c16++) {
            const int cp = head*16 + c16;
            float xa, ya;
            unpack2(acc[c16], xa, ya);
            foutbase[(size_t)(2*cp    )*HWP] = xa;
            foutbase[(size_t)(2*cp + 1)*HWP] = ya;
        }
    }
}

// ============================================================================
// Launch
// ============================================================================
extern "C" void kernel_launch(void* const* d_in, const int* in_sizes, int n_in,
                              void* d_out, int out_size)
{
    const float* x  = (const float*)d_in[0];
    const float* Wv = (const float*)d_in[1];
    const float* Wa = (const float*)d_in[2];
    const float* ba = (const float*)d_in[3];
    const float* Wp = (const float*)d_in[4];
    const float* bp = (const float*)d_in[5];
    float* out = (float*)d_out;

    float *vp, *fp, *wpad;
    __half* ap;
    cudaGetSymbolAddress((void**)&vp, g_v);
    cudaGetSymbolAddress((void**)&ap, g_att);
    cudaGetSymbolAddress((void**)&fp, g_fold);
    cudaGetSymbolAddress((void**)&wpad, g_wpad);

    cudaFuncSetAttribute(att_kernel, cudaFuncAttributeMaxDynamicSharedMemorySize, ATT_SMEM_BYTES);
    cudaFuncSetAttribute(agg_kernel, cudaFuncAttributeMaxDynamicSharedMemorySize, AGG_SMEM_BYTES);

    // pad Wa -> [192][648] fp32
    pad_wa_kernel<<<(CC*KTP + 255)/256, 256>>>(Wa, wpad);
    // value projection: v = x @ Wv
    gemm192_kernel<<<392*2, 192>>>(x, Wv, nullptr, vp);
    // attention logits + fused softmax (128px x 27-group tiles, cp.async)
    att_kernel<<<392*2, 864, ATT_SMEM_BYTES>>>(x, wpad, ba, ap);
    // aggregation + fold (collapsed 5x5 stencil, fp16 att gather)
    agg_kernel<<<NB*49, 384, AGG_SMEM_BYTES>>>(vp, ap, fp);
    // output projection: out = folded @ Wp + bp
    gemm192_kernel<<<392*2, 192>>>(fp, Wp, bp, out);
}